// round 1
// baseline (speedup 1.0000x reference)
#include <cuda_runtime.h>
#include <math.h>

#define BATCH  128
#define LSEQ   2048
#define HDIM   512
#define DDIM   512
#define TSTEPS 10
#define NWARP  16

// Inter-kernel state (allocation-free scratch)
__device__ float g_s[BATCH * HDIM];   // s / cell state
__device__ float g_h[BATCH * HDIM];   // hidden state
__device__ float g_x[BATCH * DDIM];   // next input x

// ---------------------------------------------------------------------------
// Attention: one CTA per batch row, single streaming pass over hid_states.
// u = cos(s, h_l) in [-1,1] -> no max subtraction needed in softmax.
// Computes hs_sq = sum(h_l^2) on the fly (free while data is in registers).
// s_out = s_in + (sum_l e^{u_l} h_l) / (sum_l e^{u_l})
// ---------------------------------------------------------------------------
__global__ __launch_bounds__(512) void attn_kernel(
    const float* __restrict__ hid, const float* __restrict__ s_init, int t)
{
    const int b    = blockIdx.x;
    const int lane = threadIdx.x & 31;
    const int wid  = threadIdx.x >> 5;

    const float* s_in = (t == 0) ? (s_init + (size_t)b * HDIM)
                                 : (g_s   + (size_t)b * HDIM);

    // s registers: lane j, slot k -> columns [4j+128k, 4j+128k+4)
    float4 s4[4];
#pragma unroll
    for (int k = 0; k < 4; k++)
        s4[k] = *reinterpret_cast<const float4*>(s_in + 4 * lane + 128 * k);

    float ss = 0.f;
#pragma unroll
    for (int k = 0; k < 4; k++)
        ss += s4[k].x * s4[k].x + s4[k].y * s4[k].y +
              s4[k].z * s4[k].z + s4[k].w * s4[k].w;
#pragma unroll
    for (int off = 16; off; off >>= 1)
        ss += __shfl_xor_sync(0xffffffffu, ss, off);

    const float4* base = reinterpret_cast<const float4*>(hid)
                       + (size_t)b * (size_t)LSEQ * (HDIM / 4);

    float4 acc[4];
#pragma unroll
    for (int k = 0; k < 4; k++) acc[k] = make_float4(0.f, 0.f, 0.f, 0.f);
    float Z = 0.f;

    // Double-buffered streaming over l = wid, wid+16, ...
    float4 h4[4];
    {
        const float4* hp = base + (size_t)wid * (HDIM / 4);
#pragma unroll
        for (int k = 0; k < 4; k++) h4[k] = hp[lane + 32 * k];
    }

    for (int l = wid; l < LSEQ; l += NWARP) {
        float4 n4[4];
        const int ln = l + NWARP;
        if (ln < LSEQ) {
            const float4* np = base + (size_t)ln * (HDIM / 4);
#pragma unroll
            for (int k = 0; k < 4; k++) n4[k] = np[lane + 32 * k];
        }

        float d = 0.f, hs = 0.f;
#pragma unroll
        for (int k = 0; k < 4; k++) {
            d  += s4[k].x * h4[k].x + s4[k].y * h4[k].y +
                  s4[k].z * h4[k].z + s4[k].w * h4[k].w;
            hs += h4[k].x * h4[k].x + h4[k].y * h4[k].y +
                  h4[k].z * h4[k].z + h4[k].w * h4[k].w;
        }
#pragma unroll
        for (int off = 16; off; off >>= 1) {
            d  += __shfl_xor_sync(0xffffffffu, d,  off);
            hs += __shfl_xor_sync(0xffffffffu, hs, off);
        }

        const float denom = sqrtf(hs * ss) + 1e-8f;
        const float w = __expf(d / denom);
        Z += w;
#pragma unroll
        for (int k = 0; k < 4; k++) {
            acc[k].x += w * h4[k].x; acc[k].y += w * h4[k].y;
            acc[k].z += w * h4[k].z; acc[k].w += w * h4[k].w;
        }
#pragma unroll
        for (int k = 0; k < 4; k++) h4[k] = n4[k];
    }

    // Cross-warp reduction
    __shared__ float sacc[NWARP][HDIM];
    __shared__ float sZ[NWARP];
#pragma unroll
    for (int k = 0; k < 4; k++)
        *reinterpret_cast<float4*>(&sacc[wid][4 * lane + 128 * k]) = acc[k];
    if (lane == 0) sZ[wid] = Z;   // w identical across lanes post-allreduce
    __syncthreads();

    const int col = threadIdx.x;  // 0..511
    float cs = 0.f;
#pragma unroll
    for (int w2 = 0; w2 < NWARP; w2++) cs += sacc[w2][col];
    float Zt = 0.f;
#pragma unroll
    for (int w2 = 0; w2 < NWARP; w2++) Zt += sZ[w2];

    g_s[(size_t)b * HDIM + col] = s_in[col] + cs / Zt;
}

// ---------------------------------------------------------------------------
// LSTM gates GEMM + combine.
// Tile: 32 batch rows x 16 h-cols (= 64 gate cols across i,f,g,o quadrants).
// Grid (32 hblk, 4 bblk) = 128 CTAs, 256 threads.
// Each thread: 1 gate col x 8 batch rows. Then fused LSTM combine:
//   c = sig(f)*s + sig(i)*tanh(g);  h = sig(o)*tanh(c);  g_s <- c, g_h <- h
// ---------------------------------------------------------------------------
#define GK 64   // K-chunk

__global__ __launch_bounds__(256) void gates_kernel(
    const float* __restrict__ W_ih, const float* __restrict__ W_hh,
    const float* __restrict__ b_lstm,
    const float* __restrict__ x0, const float* __restrict__ h0, int t)
{
    const int c0  = blockIdx.x * 16;   // h-col base (0..511)
    const int b0  = blockIdx.y * 32;   // batch base
    const int tid = threadIdx.x;
    const int gc  = tid & 63;          // 0..63
    const int grp = tid >> 6;          // 0..3 -> batch sub-group of 8
    const int g   = gc >> 4;           // gate id 0..3
    const int cl  = gc & 15;           // local h-col
    const int col = g * HDIM + c0 + cl;

    const float* xin = (t == 0) ? x0 : g_x;
    const float* hin = (t == 0) ? h0 : g_h;

    __shared__ float xsT[GK][33];   // [k][b_local], pad vs bank conflicts
    __shared__ float hsT[GK][33];

    float acc[8];
#pragma unroll
    for (int j = 0; j < 8; j++) acc[j] = 0.f;
    const float bias = b_lstm[col];

    for (int k0 = 0; k0 < 512; k0 += GK) {
        __syncthreads();
        {
            const int kk = tid & 63;   // 0..63 (coalesced along k)
            const int bb = tid >> 6;   // 0..3
#pragma unroll
            for (int i = 0; i < 8; i++) {
                const int br = bb + 4 * i;   // 0..31 distinct
                xsT[kk][br] = xin[(size_t)(b0 + br) * DDIM + k0 + kk];
                hsT[kk][br] = hin[(size_t)(b0 + br) * HDIM + k0 + kk];
            }
        }
        __syncthreads();

        const float* wi = W_ih + (size_t)k0 * (4 * HDIM) + col;
        const float* wh = W_hh + (size_t)k0 * (4 * HDIM) + col;
#pragma unroll 4
        for (int k = 0; k < GK; k++) {
            const float a_ih = wi[(size_t)k * (4 * HDIM)];
            const float a_hh = wh[(size_t)k * (4 * HDIM)];
#pragma unroll
            for (int j = 0; j < 8; j++) {
                acc[j] += a_ih * xsT[k][grp * 8 + j];   // smem broadcast
                acc[j] += a_hh * hsT[k][grp * 8 + j];
            }
        }
    }

    __shared__ float sg[4][32][16];
    __syncthreads();
#pragma unroll
    for (int j = 0; j < 8; j++)
        sg[g][grp * 8 + j][cl] = acc[j] + bias;
    __syncthreads();

    // Combine: 512 (b,c) pairs, 2 per thread
#pragma unroll
    for (int i = 0; i < 2; i++) {
        const int p   = tid + 256 * i;
        const int bl  = p >> 4;
        const int cl2 = p & 15;
        const int bg  = b0 + bl;
        const int cg  = c0 + cl2;

        const float gi = sg[0][bl][cl2];
        const float gf = sg[1][bl][cl2];
        const float gg = sg[2][bl][cl2];
        const float go = sg[3][bl][cl2];

        const float sv = g_s[(size_t)bg * HDIM + cg];
        const float si = 1.f / (1.f + expf(-gi));
        const float sf = 1.f / (1.f + expf(-gf));
        const float so = 1.f / (1.f + expf(-go));
        const float cv = sf * sv + si * tanhf(gg);
        const float hv = so * tanhf(cv);

        g_s[(size_t)bg * HDIM + cg] = cv;
        g_h[(size_t)bg * HDIM + cg] = hv;
    }
}

// ---------------------------------------------------------------------------
// MLP head: x = lrelu(h@W1 + b1, 0.01) @ W2 + b2; writes g_x and the
// permuted output slice for step t:  out[b, k%10, k/10] with k = t*512 + d.
// Grid 128 (CTA per batch row), 256 threads.
// ---------------------------------------------------------------------------
__global__ __launch_bounds__(256) void mlp_kernel(
    const float* __restrict__ W1, const float* __restrict__ b1,
    const float* __restrict__ W2, const float* __restrict__ b2,
    float* __restrict__ out, int t)
{
    const int b   = blockIdx.x;
    const int tid = threadIdx.x;

    __shared__ float hrow[HDIM];
    __shared__ float apart[4][64];
    __shared__ float a_s[64];

    hrow[tid]       = g_h[(size_t)b * HDIM + tid];
    hrow[tid + 256] = g_h[(size_t)b * HDIM + tid + 256];
    __syncthreads();

    {
        const int j   = tid & 63;
        const int seg = tid >> 6;    // k in [seg*128, seg*128+128)
        float p = 0.f;
        const float* w = W1 + (size_t)(seg * 128) * 64 + j;
#pragma unroll 8
        for (int kk = 0; kk < 128; kk++)
            p += hrow[seg * 128 + kk] * w[(size_t)kk * 64];
        apart[seg][j] = p;
    }
    __syncthreads();
    if (tid < 64) {
        const float v = apart[0][tid] + apart[1][tid] +
                        apart[2][tid] + apart[3][tid] + b1[tid];
        a_s[tid] = (v > 0.f) ? v : 0.01f * v;
    }
    __syncthreads();

#pragma unroll
    for (int i = 0; i < 2; i++) {
        const int d = tid + 256 * i;
        float v = b2[d];
#pragma unroll 8
        for (int j = 0; j < 64; j++)
            v += a_s[j] * W2[(size_t)j * 512 + d];

        g_x[(size_t)b * DDIM + d] = v;

        const int k  = t * DDIM + d;       // 0..5119
        const int ii = k / 10;
        const int jj = k - 10 * ii;
        out[((size_t)b * TSTEPS + jj) * 512 + ii] = v;
    }
}

// ---------------------------------------------------------------------------
extern "C" void kernel_launch(void* const* d_in, const int* in_sizes, int n_in,
                              void* d_out, int out_size)
{
    const float* batch  = (const float*)d_in[0];
    const float* hid    = (const float*)d_in[1];
    const float* h0     = (const float*)d_in[2];
    const float* s0     = (const float*)d_in[3];
    const float* W_ih   = (const float*)d_in[4];
    const float* W_hh   = (const float*)d_in[5];
    const float* b_lstm = (const float*)d_in[6];
    const float* W1     = (const float*)d_in[7];
    const float* b1     = (const float*)d_in[8];
    const float* W2     = (const float*)d_in[9];
    const float* b2     = (const float*)d_in[10];
    float* out = (float*)d_out;

    for (int t = 0; t < TSTEPS; t++) {
        attn_kernel <<<BATCH, 512>>>(hid, s0, t);
        gates_kernel<<<dim3(32, 4), 256>>>(W_ih, W_hh, b_lstm, batch, h0, t);
        mlp_kernel  <<<BATCH, 256>>>(W1, b1, W2, b2, out, t);
    }
}

// round 2
// speedup vs baseline: 1.9765x; 1.9765x over previous
#include <cuda_runtime.h>
#include <cuda_fp16.h>
#include <math.h>

#define BATCH  128
#define LSEQ   2048
#define HDIM   512
#define DDIM   512
#define TSTEPS 10
#define NWARP  16
#define SPLITS 8
#define KC     128   // K per split
#define BN     128   // GEMM N tile
#define KB     16    // GEMM k sub-tile

// Inter-kernel state (allocation-free scratch; module globals)
__device__ float g_s[BATCH * HDIM];                 // s / cell state
__device__ float g_h[BATCH * HDIM];                 // hidden state
__device__ float g_x[BATCH * DDIM];                 // next input x
__device__ float g_part[SPLITS * BATCH * 4 * HDIM]; // GEMM split-K partials (8MB)
__device__ __align__(16) __half g_hid16[(size_t)BATCH * LSEQ * HDIM]; // 256MB fp16 copy

// ---------------------------------------------------------------------------
// Attention step 0: stream fp32 hid_states, do the cosine-softmax context,
// and write the fp16 copy of hid_states for steps 1..9 in the same pass.
// u = cos(s,h_l) in [-1,1] -> softmax needs no running max.
// ---------------------------------------------------------------------------
__global__ __launch_bounds__(512) void attn0_kernel(
    const float* __restrict__ hid, const float* __restrict__ s_init)
{
    const int b    = blockIdx.x;
    const int lane = threadIdx.x & 31;
    const int wid  = threadIdx.x >> 5;

    const float* s_in = s_init + (size_t)b * HDIM;

    // lane j, slot k -> columns [4j+128k, 4j+128k+4)
    float4 s4[4];
#pragma unroll
    for (int k = 0; k < 4; k++)
        s4[k] = *reinterpret_cast<const float4*>(s_in + 4 * lane + 128 * k);

    float ss = 0.f;
#pragma unroll
    for (int k = 0; k < 4; k++)
        ss += s4[k].x * s4[k].x + s4[k].y * s4[k].y +
              s4[k].z * s4[k].z + s4[k].w * s4[k].w;
#pragma unroll
    for (int off = 16; off; off >>= 1)
        ss += __shfl_xor_sync(0xffffffffu, ss, off);

    const float4* base = reinterpret_cast<const float4*>(hid)
                       + (size_t)b * (size_t)LSEQ * (HDIM / 4);
    __half* out16 = g_hid16 + (size_t)b * (size_t)LSEQ * HDIM;

    float4 acc[4];
#pragma unroll
    for (int k = 0; k < 4; k++) acc[k] = make_float4(0.f, 0.f, 0.f, 0.f);
    float Z = 0.f;

    float4 h4[4];
    {
        const float4* hp = base + (size_t)wid * (HDIM / 4);
#pragma unroll
        for (int k = 0; k < 4; k++) h4[k] = hp[lane + 32 * k];
    }

    for (int l = wid; l < LSEQ; l += NWARP) {
        float4 n4[4];
        const int ln = l + NWARP;
        if (ln < LSEQ) {
            const float4* np = base + (size_t)ln * (HDIM / 4);
#pragma unroll
            for (int k = 0; k < 4; k++) n4[k] = np[lane + 32 * k];
        }

        float d = 0.f, hs = 0.f;
#pragma unroll
        for (int k = 0; k < 4; k++) {
            d  += s4[k].x * h4[k].x + s4[k].y * h4[k].y +
                  s4[k].z * h4[k].z + s4[k].w * h4[k].w;
            hs += h4[k].x * h4[k].x + h4[k].y * h4[k].y +
                  h4[k].z * h4[k].z + h4[k].w * h4[k].w;
        }
#pragma unroll
        for (int off = 16; off; off >>= 1) {
            d  += __shfl_xor_sync(0xffffffffu, d,  off);
            hs += __shfl_xor_sync(0xffffffffu, hs, off);
        }

        // write fp16 copy of this row chunk (cols 4*lane+128k .. +4)
#pragma unroll
        for (int k = 0; k < 4; k++) {
            __half2 a = __floats2half2_rn(h4[k].x, h4[k].y);
            __half2 c = __floats2half2_rn(h4[k].z, h4[k].w);
            uint2 pk;
            pk.x = *reinterpret_cast<unsigned*>(&a);
            pk.y = *reinterpret_cast<unsigned*>(&c);
            *reinterpret_cast<uint2*>(out16 + (size_t)l * HDIM + 128 * k + 4 * lane) = pk;
        }

        const float denom = sqrtf(hs * ss) + 1e-8f;
        const float w = __expf(d / denom);
        Z += w;
#pragma unroll
        for (int k = 0; k < 4; k++) {
            acc[k].x += w * h4[k].x; acc[k].y += w * h4[k].y;
            acc[k].z += w * h4[k].z; acc[k].w += w * h4[k].w;
        }
#pragma unroll
        for (int k = 0; k < 4; k++) h4[k] = n4[k];
    }

    __shared__ float sacc[NWARP][HDIM];
    __shared__ float sZ[NWARP];
#pragma unroll
    for (int k = 0; k < 4; k++)
        *reinterpret_cast<float4*>(&sacc[wid][4 * lane + 128 * k]) = acc[k];
    if (lane == 0) sZ[wid] = Z;
    __syncthreads();

    const int col = threadIdx.x;
    float cs = 0.f;
#pragma unroll
    for (int w2 = 0; w2 < NWARP; w2++) cs += sacc[w2][col];
    float Zt = 0.f;
#pragma unroll
    for (int w2 = 0; w2 < NWARP; w2++) Zt += sZ[w2];

    g_s[(size_t)b * HDIM + col] = s_in[col] + cs / Zt;
}

// ---------------------------------------------------------------------------
// Attention steps 1..9: stream the fp16 copy (half the traffic).
// lane covers halves [8*lane, 8*lane+8) and [256+8*lane, 256+8*lane+8).
// ---------------------------------------------------------------------------
__global__ __launch_bounds__(512) void attn16_kernel()
{
    const int b    = blockIdx.x;
    const int lane = threadIdx.x & 31;
    const int wid  = threadIdx.x >> 5;

    const float* s_in = g_s + (size_t)b * HDIM;

    float sv[16];
#pragma unroll
    for (int k = 0; k < 2; k++) {
        float4 a = *reinterpret_cast<const float4*>(s_in + 256 * k + 8 * lane);
        float4 c = *reinterpret_cast<const float4*>(s_in + 256 * k + 8 * lane + 4);
        sv[8*k+0]=a.x; sv[8*k+1]=a.y; sv[8*k+2]=a.z; sv[8*k+3]=a.w;
        sv[8*k+4]=c.x; sv[8*k+5]=c.y; sv[8*k+6]=c.z; sv[8*k+7]=c.w;
    }
    float ss = 0.f;
#pragma unroll
    for (int k = 0; k < 16; k++) ss += sv[k] * sv[k];
#pragma unroll
    for (int off = 16; off; off >>= 1)
        ss += __shfl_xor_sync(0xffffffffu, ss, off);

    const uint4* base = reinterpret_cast<const uint4*>(g_hid16)
                      + (size_t)b * (size_t)LSEQ * (HDIM / 8);

    float accv[16];
#pragma unroll
    for (int k = 0; k < 16; k++) accv[k] = 0.f;
    float Z = 0.f;

    uint4 hb[2];
    {
        const uint4* hp = base + (size_t)wid * (HDIM / 8);
        hb[0] = hp[lane]; hb[1] = hp[lane + 32];
    }

    for (int l = wid; l < LSEQ; l += NWARP) {
        uint4 nb[2];
        const int ln = l + NWARP;
        if (ln < LSEQ) {
            const uint4* np = base + (size_t)ln * (HDIM / 8);
            nb[0] = np[lane]; nb[1] = np[lane + 32];
        }

        float hv[16];
#pragma unroll
        for (int k = 0; k < 2; k++) {
            const unsigned* u = reinterpret_cast<const unsigned*>(&hb[k]);
#pragma unroll
            for (int q = 0; q < 4; q++) {
                __half2 p = *reinterpret_cast<const __half2*>(&u[q]);
                float2 f = __half22float2(p);
                hv[8*k + 2*q]     = f.x;
                hv[8*k + 2*q + 1] = f.y;
            }
        }

        float d = 0.f, hs = 0.f;
#pragma unroll
        for (int k = 0; k < 16; k++) {
            d  += sv[k] * hv[k];
            hs += hv[k] * hv[k];
        }
#pragma unroll
        for (int off = 16; off; off >>= 1) {
            d  += __shfl_xor_sync(0xffffffffu, d,  off);
            hs += __shfl_xor_sync(0xffffffffu, hs, off);
        }

        const float denom = sqrtf(hs * ss) + 1e-8f;
        const float w = __expf(d / denom);
        Z += w;
#pragma unroll
        for (int k = 0; k < 16; k++) accv[k] += w * hv[k];

        hb[0] = nb[0]; hb[1] = nb[1];
    }

    __shared__ float sacc[NWARP][HDIM];
    __shared__ float sZ[NWARP];
#pragma unroll
    for (int k = 0; k < 2; k++) {
        *reinterpret_cast<float4*>(&sacc[wid][256*k + 8*lane])     =
            make_float4(accv[8*k+0], accv[8*k+1], accv[8*k+2], accv[8*k+3]);
        *reinterpret_cast<float4*>(&sacc[wid][256*k + 8*lane + 4]) =
            make_float4(accv[8*k+4], accv[8*k+5], accv[8*k+6], accv[8*k+7]);
    }
    if (lane == 0) sZ[wid] = Z;
    __syncthreads();

    const int col = threadIdx.x;
    float cs = 0.f;
#pragma unroll
    for (int w2 = 0; w2 < NWARP; w2++) cs += sacc[w2][col];
    float Zt = 0.f;
#pragma unroll
    for (int w2 = 0; w2 < NWARP; w2++) Zt += sZ[w2];

    g_s[(size_t)b * HDIM + col] = s_in[col] + cs / Zt;
}

// ---------------------------------------------------------------------------
// Gates GEMM, split-K: C[128 x 2048] = [x|h][128 x 1024] @ [W_ih;W_hh].
// Grid (16 n-blocks, 8 k-splits), 256 threads, BM=128, BN=128, 8x8 per thread.
// Each CTA writes its 128x128 partial to g_part[split].
// ---------------------------------------------------------------------------
__global__ __launch_bounds__(256) void gemm_kernel(
    const float* __restrict__ W_ih, const float* __restrict__ W_hh,
    const float* __restrict__ x0, const float* __restrict__ h0, int t)
{
    const int n0  = blockIdx.x * BN;
    const int sp  = blockIdx.y;
    const int kg0 = sp * KC;
    const bool isX = (kg0 < 512);
    const float* A = isX ? ((t == 0) ? x0 : g_x) : ((t == 0) ? h0 : g_h);
    const float* W = isX ? W_ih : W_hh;
    const int ka0 = isX ? kg0 : (kg0 - 512);

    __shared__ float As[KB][128];   // [k][m]
    __shared__ float Bs[KB][BN];    // [k][n]

    const int tid = threadIdx.x;
    const int tx  = tid & 15;       // n subtile
    const int ty  = tid >> 4;       // m subtile

    float acc[8][8];
#pragma unroll
    for (int i = 0; i < 8; i++)
#pragma unroll
        for (int j = 0; j < 8; j++) acc[i][j] = 0.f;

    for (int kb = 0; kb < KC; kb += KB) {
        {   // A tile: 128 x 16, store transposed
            const int m  = tid >> 1;
            const int ko = (tid & 1) * 8;
            const float* ap = A + (size_t)m * 512 + ka0 + kb + ko;
            float4 v0 = *reinterpret_cast<const float4*>(ap);
            float4 v1 = *reinterpret_cast<const float4*>(ap + 4);
            As[ko+0][m] = v0.x; As[ko+1][m] = v0.y;
            As[ko+2][m] = v0.z; As[ko+3][m] = v0.w;
            As[ko+4][m] = v1.x; As[ko+5][m] = v1.y;
            As[ko+6][m] = v1.z; As[ko+7][m] = v1.w;
        }
        {   // B tile: 16 x 128
#pragma unroll
            for (int it = 0; it < 2; it++) {
                const int kk = (tid >> 5) + it * 8;
                const int c  = (tid & 31) * 4;
                *reinterpret_cast<float4*>(&Bs[kk][c]) =
                    *reinterpret_cast<const float4*>(
                        W + (size_t)(ka0 + kb + kk) * (4 * HDIM) + n0 + c);
            }
        }
        __syncthreads();

#pragma unroll
        for (int kk = 0; kk < KB; kk++) {
            float a[8], bf[8];
            *reinterpret_cast<float4*>(a)      = *reinterpret_cast<float4*>(&As[kk][ty*8]);
            *reinterpret_cast<float4*>(a + 4)  = *reinterpret_cast<float4*>(&As[kk][ty*8+4]);
            *reinterpret_cast<float4*>(bf)     = *reinterpret_cast<float4*>(&Bs[kk][tx*8]);
            *reinterpret_cast<float4*>(bf + 4) = *reinterpret_cast<float4*>(&Bs[kk][tx*8+4]);
#pragma unroll
            for (int i = 0; i < 8; i++)
#pragma unroll
                for (int j = 0; j < 8; j++)
                    acc[i][j] += a[i] * bf[j];
        }
        __syncthreads();
    }

    float* P = g_part + (size_t)sp * BATCH * (4 * HDIM);
#pragma unroll
    for (int i = 0; i < 8; i++) {
        const int m = ty * 8 + i;
#pragma unroll
        for (int j = 0; j < 8; j += 4)
            *reinterpret_cast<float4*>(&P[(size_t)m * (4*HDIM) + n0 + tx*8 + j]) =
                make_float4(acc[i][j], acc[i][j+1], acc[i][j+2], acc[i][j+3]);
    }
}

// ---------------------------------------------------------------------------
// Combine: reduce 8 split-K partials + bias -> gates -> LSTM cell update.
// Grid 128 (batch), 512 threads (h-col).
// ---------------------------------------------------------------------------
__global__ __launch_bounds__(512) void combine_kernel(
    const float* __restrict__ b_lstm)
{
    const int b  = blockIdx.x;
    const int ch = threadIdx.x;

    float gv[4];
#pragma unroll
    for (int g = 0; g < 4; g++) {
        float v = b_lstm[g * HDIM + ch];
#pragma unroll
        for (int sp = 0; sp < SPLITS; sp++)
            v += g_part[((size_t)sp * BATCH + b) * (4*HDIM) + g * HDIM + ch];
        gv[g] = v;
    }

    const float sv = g_s[(size_t)b * HDIM + ch];
    const float si = 1.f / (1.f + expf(-gv[0]));
    const float sf = 1.f / (1.f + expf(-gv[1]));
    const float so = 1.f / (1.f + expf(-gv[3]));
    const float cv = sf * sv + si * tanhf(gv[2]);
    const float hv = so * tanhf(cv);

    g_s[(size_t)b * HDIM + ch] = cv;
    g_h[(size_t)b * HDIM + ch] = hv;
}

// ---------------------------------------------------------------------------
// MLP head: x = lrelu(h@W1 + b1, 0.01) @ W2 + b2; writes g_x and the
// permuted output slice for step t: out[b, k%10, k/10], k = t*512 + d.
// ---------------------------------------------------------------------------
__global__ __launch_bounds__(256) void mlp_kernel(
    const float* __restrict__ W1, const float* __restrict__ b1,
    const float* __restrict__ W2, const float* __restrict__ b2,
    float* __restrict__ out, int t)
{
    const int b   = blockIdx.x;
    const int tid = threadIdx.x;

    __shared__ float hrow[HDIM];
    __shared__ float apart[4][64];
    __shared__ float a_s[64];

    hrow[tid]       = g_h[(size_t)b * HDIM + tid];
    hrow[tid + 256] = g_h[(size_t)b * HDIM + tid + 256];
    __syncthreads();

    {
        const int j   = tid & 63;
        const int seg = tid >> 6;
        float p = 0.f;
        const float* w = W1 + (size_t)(seg * 128) * 64 + j;
#pragma unroll 8
        for (int kk = 0; kk < 128; kk++)
            p += hrow[seg * 128 + kk] * w[(size_t)kk * 64];
        apart[seg][j] = p;
    }
    __syncthreads();
    if (tid < 64) {
        const float v = apart[0][tid] + apart[1][tid] +
                        apart[2][tid] + apart[3][tid] + b1[tid];
        a_s[tid] = (v > 0.f) ? v : 0.01f * v;
    }
    __syncthreads();

#pragma unroll
    for (int i = 0; i < 2; i++) {
        const int d = tid + 256 * i;
        float v = b2[d];
#pragma unroll 8
        for (int j = 0; j < 64; j++)
            v += a_s[j] * W2[(size_t)j * 512 + d];

        g_x[(size_t)b * DDIM + d] = v;

        const int k  = t * DDIM + d;
        const int ii = k / 10;
        const int jj = k - 10 * ii;
        out[((size_t)b * TSTEPS + jj) * 512 + ii] = v;
    }
}

// ---------------------------------------------------------------------------
extern "C" void kernel_launch(void* const* d_in, const int* in_sizes, int n_in,
                              void* d_out, int out_size)
{
    const float* batch  = (const float*)d_in[0];
    const float* hid    = (const float*)d_in[1];
    const float* h0     = (const float*)d_in[2];
    const float* s0     = (const float*)d_in[3];
    const float* W_ih   = (const float*)d_in[4];
    const float* W_hh   = (const float*)d_in[5];
    const float* b_lstm = (const float*)d_in[6];
    const float* W1     = (const float*)d_in[7];
    const float* b1     = (const float*)d_in[8];
    const float* W2     = (const float*)d_in[9];
    const float* b2     = (const float*)d_in[10];
    float* out = (float*)d_out;

    for (int t = 0; t < TSTEPS; t++) {
        if (t == 0) attn0_kernel<<<BATCH, 512>>>(hid, s0);
        else        attn16_kernel<<<BATCH, 512>>>();
        gemm_kernel<<<dim3(16, SPLITS), 256>>>(W_ih, W_hh, batch, h0, t);
        combine_kernel<<<BATCH, 512>>>(b_lstm);
        mlp_kernel<<<BATCH, 256>>>(W1, b1, W2, b2, out, t);
    }
}